// round 13
// baseline (speedup 1.0000x reference)
#include <cuda_runtime.h>
#include <cuda_fp16.h>
#include <cstdint>
#include <cstddef>

// Problem dims
#define NQ 8192
#define MC 20000
#define MP 20096            // centers padded: 157*128
#define DD 1024
#define YY 256
#define PADW 20             // smem row stride in 32-bit words (conflict-free walk)

// GEMM1 staging geometry: stage = A[128 rows x 20 words] + B[128 x 20]
#define ROWW 20                       // words per row (16 data + 4 pad)
#define HALF_STG (128 * ROWW)         // words: one operand block (2560 w = 10240 B)
#define STG_W (2 * HALF_STG)          // words per stage (5120 w = 20480 B)
#define NSTG 3
#define SMEM1_BYTES (NSTG * STG_W * 4)  // 61440

// Scratch (device globals; zero-initialized at load)
__device__ __half g_K[(size_t)NQ * MP];    // fp16 kernel matrix
__device__ __half g_Wt[(size_t)YY * MP];   // W transposed, k-contiguous; tail 0
__device__ __half g_Xh[(size_t)NQ * DD];   // fp16 batch
__device__ __half g_Zh[(size_t)MP * DD];   // fp16 centers; tail rows stay 0
__device__ float  g_xsq[NQ];
__device__ float  g_zsq[MP];               // tail stays 0

// ---------------------------------------------------------------------------
// Helpers
// ---------------------------------------------------------------------------
__device__ __forceinline__ void mma_f16_f32(float* c, const uint32_t* a, const uint32_t* b) {
    asm volatile(
        "mma.sync.aligned.m16n8k16.row.col.f32.f16.f16.f32 "
        "{%0,%1,%2,%3},{%4,%5,%6,%7},{%8,%9},{%0,%1,%2,%3};"
        : "+f"(c[0]), "+f"(c[1]), "+f"(c[2]), "+f"(c[3])
        : "r"(a[0]), "r"(a[1]), "r"(a[2]), "r"(a[3]), "r"(b[0]), "r"(b[1]));
}

__device__ __forceinline__ void mma_f16_f16(uint32_t* c, const uint32_t* a, const uint32_t* b) {
    asm volatile(
        "mma.sync.aligned.m16n8k16.row.col.f16.f16.f16.f16 "
        "{%0,%1},{%2,%3,%4,%5},{%6,%7},{%0,%1};"
        : "+r"(c[0]), "+r"(c[1])
        : "r"(a[0]), "r"(a[1]), "r"(a[2]), "r"(a[3]), "r"(b[0]), "r"(b[1]));
}

__device__ __forceinline__ uint32_t smem_u32(const void* p) {
    uint32_t a;
    asm("{ .reg .u64 t; cvta.to.shared.u64 t, %1; cvt.u32.u64 %0, t; }" : "=r"(a) : "l"(p));
    return a;
}

__device__ __forceinline__ void cp_async16(uint32_t dst, const void* src) {
    asm volatile("cp.async.cg.shared.global [%0], [%1], 16;" :: "r"(dst), "l"(src));
}
__device__ __forceinline__ void cpa_commit() {
    asm volatile("cp.async.commit_group;" ::: "memory");
}
__device__ __forceinline__ void cpa_wait1() {
    asm volatile("cp.async.wait_group 1;" ::: "memory");
}
__device__ __forceinline__ void cpa_wait0() {
    asm volatile("cp.async.wait_group 0;" ::: "memory");
}

__device__ __forceinline__ uint32_t h2u(__half2 h) {
    return *reinterpret_cast<uint32_t*>(&h);
}

__device__ __forceinline__ float resolve_bw(const void* p) {
    int iv = *(const int*)p;
    if (iv > 0 && iv < 1000000) return (float)iv;
    return *(const float*)p;
}

// ---------------------------------------------------------------------------
// Kernel 0: convert fp32 rows -> fp16 AND compute exact fp32 row sq-norms.
// ---------------------------------------------------------------------------
__global__ void convert_kernel(const float* __restrict__ x, const float* __restrict__ z) {
    int gwarp = (blockIdx.x * blockDim.x + threadIdx.x) >> 5;
    int lane = threadIdx.x & 31;
    const float* src;
    __half* dh;
    float* dsq;
    if (gwarp < NQ) {
        src = x + (size_t)gwarp * DD; dh = g_Xh + (size_t)gwarp * DD; dsq = g_xsq + gwarp;
    } else if (gwarp < NQ + MC) {
        int r = gwarp - NQ;
        src = z + (size_t)r * DD;     dh = g_Zh + (size_t)r * DD;     dsq = g_zsq + r;
    } else return;

    const float4* p = (const float4*)src;
    uint2* o = (uint2*)dh;
    float s = 0.f;
#pragma unroll
    for (int i = 0; i < DD / 128; i++) {
        float4 v = p[lane + i * 32];
        s += v.x * v.x + v.y * v.y + v.z * v.z + v.w * v.w;
        o[lane + i * 32] = make_uint2(h2u(__floats2half2_rn(v.x, v.y)),
                                      h2u(__floats2half2_rn(v.z, v.w)));
    }
#pragma unroll
    for (int off = 16; off; off >>= 1) s += __shfl_xor_sync(0xffffffffu, s, off);
    if (lane == 0) *dsq = s;
}

// ---------------------------------------------------------------------------
// Kernel 0b: transpose W [MC, YY] fp32 -> g_Wt [YY, MP] fp16
// ---------------------------------------------------------------------------
__global__ void wtrans_kernel(const float* __restrict__ W) {
    __shared__ float t[32][33];
    const int k0 = blockIdx.x * 32;
    const int n0 = blockIdx.y * 32;
    const int tx = threadIdx.x, ty = threadIdx.y;
    t[ty][tx] = W[(size_t)(k0 + ty) * YY + (n0 + tx)];
    __syncthreads();
    g_Wt[(size_t)(n0 + ty) * MP + (k0 + tx)] = __float2half_rn(t[tx][ty]);
}

// ---------------------------------------------------------------------------
// Kernel 1: K[i,j] = exp(-sqrt(max(xsq+zsq-2*X.Z,0))/bw), fp16 out.
// NT GEMM fp16, f16 accumulators. BM=BN=128, BK=32, 4 warps, WARP TILE 64x64
// (halves smem-crossbar bytes/MAC vs 64x32). cp.async 3-stage ring (no LDG
// staging registers, no STS). Grid (64, 157), 128 threads, 3 CTAs/SM.
// ---------------------------------------------------------------------------
__global__ __launch_bounds__(128, 3)
void laplace_gemm_kernel(const void* __restrict__ bwp) {
    extern __shared__ uint32_t smw[];   // NSTG stages: [A 128x20w][B 128x20w]
    const uint32_t sb0 = smem_u32(smw);

    const int bm = blockIdx.x;      // 0..63
    const int bn = blockIdx.y;      // 0..156
    const int tid = threadIdx.x;    // 0..127
    const int lane = tid & 31;
    const int wid = tid >> 5;       // 0..3
    const int wm = (wid & 1) * 64;
    const int wn = (wid >> 1) * 64;

    uint32_t acc[4][8][2];          // f16x2 accumulators, warp tile 64x64
#pragma unroll
    for (int mt = 0; mt < 4; mt++)
#pragma unroll
        for (int nt = 0; nt < 8; nt++) { acc[mt][nt][0] = 0u; acc[mt][nt][1] = 0u; }

    // Each thread stages one 64B row-chunk of A (row tid) and of B per kt.
    const __half* xg = g_Xh + (size_t)(bm * 128 + tid) * DD;
    const __half* zg = g_Zh + (size_t)(bn * 128 + tid) * DD;
    const uint32_t a_dst_off = (uint32_t)tid * (ROWW * 4);
    const uint32_t b_dst_off = HALF_STG * 4 + a_dst_off;

    const int KT = DD / 32;   // 32

    // issue stage s for chunk kt
    auto issue = [&](int kt, int s) {
        const uint32_t sb = sb0 + (uint32_t)s * (STG_W * 4);
        const __half* ag = xg + kt * 32;
        const __half* bg = zg + kt * 32;
#pragma unroll
        for (int j = 0; j < 4; j++) cp_async16(sb + a_dst_off + j * 16, (const char*)ag + j * 16);
#pragma unroll
        for (int j = 0; j < 4; j++) cp_async16(sb + b_dst_off + j * 16, (const char*)bg + j * 16);
        cpa_commit();
    };

    issue(0, 0);
    issue(1, 1);

    const int frow = lane >> 2;
    const int kbase = lane & 3;

    for (int kt = 0; kt < KT; kt++) {
        if (kt < KT - 1) cpa_wait1(); else cpa_wait0();
        __syncthreads();
        if (kt + 2 < KT) issue(kt + 2, (kt + 2) % NSTG);

        const uint32_t* sa = smw + (size_t)(kt % NSTG) * STG_W;
        const uint32_t* sbp = sa + HALF_STG;

#pragma unroll
        for (int kk = 0; kk < 2; kk++) {
            const int kw = kk * 8 + kbase;
            uint32_t a[4][4], b[8][2];
#pragma unroll
            for (int mt = 0; mt < 4; mt++) {
                const int r = wm + mt * 16 + frow;
                a[mt][0] = sa[r * ROWW + kw];
                a[mt][1] = sa[(r + 8) * ROWW + kw];
                a[mt][2] = sa[r * ROWW + kw + 4];
                a[mt][3] = sa[(r + 8) * ROWW + kw + 4];
            }
#pragma unroll
            for (int nt = 0; nt < 8; nt++) {
                const int c = wn + nt * 8 + frow;
                b[nt][0] = sbp[c * ROWW + kw];
                b[nt][1] = sbp[c * ROWW + kw + 4];
            }
#pragma unroll
            for (int mt = 0; mt < 4; mt++)
#pragma unroll
                for (int nt = 0; nt < 8; nt++)
                    mma_f16_f16(acc[mt][nt], a[mt], b[nt]);
        }
        __syncthreads();
    }

    // Epilogue: unpack f16 dot, d2 -> exp(-d/bw) -> g_K (fp16)
    const float inv_bw = 1.0f / resolve_bw(bwp);
#pragma unroll
    for (int mt = 0; mt < 4; mt++) {
        const int r0 = bm * 128 + wm + mt * 16 + frow;
        const float xs0 = g_xsq[r0];
        const float xs1 = g_xsq[r0 + 8];
#pragma unroll
        for (int nt = 0; nt < 8; nt++) {
            const int c0 = bn * 128 + wn + nt * 8 + (kbase << 1);
            const float zs0 = g_zsq[c0];
            const float zs1 = g_zsq[c0 + 1];
            float2 v0 = __half22float2(*(__half2*)&acc[mt][nt][0]);
            float2 v1 = __half22float2(*(__half2*)&acc[mt][nt][1]);
            float f0 = __expf(-sqrtf(fmaxf(xs0 + zs0 - 2.f * v0.x, 0.f)) * inv_bw);
            float f1 = __expf(-sqrtf(fmaxf(xs0 + zs1 - 2.f * v0.y, 0.f)) * inv_bw);
            *(__half2*)&g_K[(size_t)r0 * MP + c0] = __floats2half2_rn(f0, f1);
            f0 = __expf(-sqrtf(fmaxf(xs1 + zs0 - 2.f * v1.x, 0.f)) * inv_bw);
            f1 = __expf(-sqrtf(fmaxf(xs1 + zs1 - 2.f * v1.y, 0.f)) * inv_bw);
            *(__half2*)&g_K[(size_t)(r0 + 8) * MP + c0] = __floats2half2_rn(f0, f1);
        }
    }
}

// ---------------------------------------------------------------------------
// Kernel 2: pred = K @ W  (NT: A=g_K fp16 [NQ,MP], B=g_Wt fp16 [YY,MP]).
// BM=32, BN=128, BK=32, 128 threads, grid (256, 2). (R12 config, unchanged.)
// ---------------------------------------------------------------------------
__global__ __launch_bounds__(128, 4)
void wgemm_kernel(float* __restrict__ out) {
    __shared__ uint32_t As[2][32][PADW];
    __shared__ uint32_t Bs[2][128][PADW];

    const int bm = blockIdx.x;   // 0..255
    const int bn = blockIdx.y;   // 0..1
    const int tid = threadIdx.x;
    const int lane = tid & 31;
    const int wid = tid >> 5;    // 0..3
    const int wn = wid * 32;

    float acc[2][4][4];
#pragma unroll
    for (int mt = 0; mt < 2; mt++)
#pragma unroll
        for (int nt = 0; nt < 4; nt++)
#pragma unroll
            for (int i = 0; i < 4; i++) acc[mt][nt][i] = 0.f;

    const int alr = tid >> 2;
    const int awo = (tid & 3) * 4;
    const size_t abase = (size_t)(bm * 32 + alr) * MP + awo * 2;
    const size_t bbase = (size_t)(bn * 128 + tid) * MP;

    uint4 ua = *(const uint4*)(g_K + abase);
    uint4 ub[4];
#pragma unroll
    for (int j = 0; j < 4; j++) ub[j] = *(const uint4*)(g_Wt + bbase + j * 8);
    *(uint4*)&As[0][alr][awo] = ua;
#pragma unroll
    for (int j = 0; j < 4; j++) *(uint4*)&Bs[0][tid][j * 4] = ub[j];
    __syncthreads();

    const int KT = MP / 32;   // 628
    for (int kt = 0; kt < KT; kt++) {
        const int buf = kt & 1;
        if (kt + 1 < KT) {
            const size_t off = (size_t)(kt + 1) * 32;
            ua = *(const uint4*)(g_K + abase + off);
#pragma unroll
            for (int j = 0; j < 4; j++) ub[j] = *(const uint4*)(g_Wt + bbase + off + j * 8);
        }

#pragma unroll
        for (int kk = 0; kk < 2; kk++) {
            const int kw = kk * 8 + (lane & 3);
            const int frow = lane >> 2;
            uint32_t a[2][4], b[4][2];
#pragma unroll
            for (int mt = 0; mt < 2; mt++) {
                int r = mt * 16 + frow;
                a[mt][0] = As[buf][r][kw];
                a[mt][1] = As[buf][r + 8][kw];
                a[mt][2] = As[buf][r][kw + 4];
                a[mt][3] = As[buf][r + 8][kw + 4];
            }
#pragma unroll
            for (int nt = 0; nt < 4; nt++) {
                int c = wn + nt * 8 + frow;
                b[nt][0] = Bs[buf][c][kw];
                b[nt][1] = Bs[buf][c][kw + 4];
            }
#pragma unroll
            for (int mt = 0; mt < 2; mt++)
#pragma unroll
                for (int nt = 0; nt < 4; nt++)
                    mma_f16_f32(acc[mt][nt], a[mt], b[nt]);
        }

        if (kt + 1 < KT) {
            const int nb = buf ^ 1;
            *(uint4*)&As[nb][alr][awo] = ua;
#pragma unroll
            for (int j = 0; j < 4; j++) *(uint4*)&Bs[nb][tid][j * 4] = ub[j];
        }
        __syncthreads();
    }

#pragma unroll
    for (int mt = 0; mt < 2; mt++) {
        const int r0 = bm * 32 + mt * 16 + (lane >> 2);
#pragma unroll
        for (int nt = 0; nt < 4; nt++) {
            const int c0 = bn * 128 + wn + nt * 8 + ((lane & 3) << 1);
            *(float2*)(out + (size_t)r0 * YY + c0) =
                make_float2(acc[mt][nt][0], acc[mt][nt][1]);
            *(float2*)(out + (size_t)(r0 + 8) * YY + c0) =
                make_float2(acc[mt][nt][2], acc[mt][nt][3]);
        }
    }
}

// ---------------------------------------------------------------------------
// Entry point (graph-capturable: launches only)
// ---------------------------------------------------------------------------
extern "C" void kernel_launch(void* const* d_in, const int* in_sizes, int n_in,
                              void* d_out, int out_size) {
    const float* batch   = (const float*)d_in[0];
    const float* centers = (const float*)d_in[1];
    const float* weight  = (const float*)d_in[2];
    const void*  bwp     = d_in[3];

    {
        int warps = NQ + MC;
        int blocks = (warps * 32 + 255) / 256;
        convert_kernel<<<blocks, 256>>>(batch, centers);
    }
    {
        dim3 grid(MC / 32, YY / 32);            // (625, 8)
        wtrans_kernel<<<grid, dim3(32, 32)>>>(weight);
    }
    {
        static bool attr_set = false;
        if (!attr_set) {
            cudaFuncSetAttribute(laplace_gemm_kernel,
                                 cudaFuncAttributeMaxDynamicSharedMemorySize, SMEM1_BYTES);
            attr_set = true;
        }
        dim3 grid(NQ / 128, (MC + 127) / 128);  // (64, 157)
        laplace_gemm_kernel<<<grid, 128, SMEM1_BYTES>>>(bwp);
    }
    {
        dim3 grid(NQ / 32, YY / 128);           // (256, 2)
        wgemm_kernel<<<grid, 128>>>((float*)d_out);
    }
}